// round 6
// baseline (speedup 1.0000x reference)
#include <cuda_runtime.h>
#include <cuda_bf16.h>
#include <math_constants.h>

#define B_      8
#define N_      8192
#define S_      2048
#define K_      16
#define DIN_    64
#define DOUT_   128
#define BN_EPS_ 1e-5f

#define FCTA_   2               // CTAs per batch (cluster size)
#define FTPB_   512             // FPS threads per CTA
#define FPPC_   (N_ / FCTA_)    // 4096 points owned per CTA
#define FPPT_   (FPPC_ / FTPB_) // 8 points per thread

// ---------------- scratch (static __device__ — no allocation allowed) ----------------
__device__ int   g_fps_idx[B_ * S_];
__device__ int   g_knn_idx[B_ * S_ * K_];
__device__ float g_h[B_ * N_ * DOUT_];   // 33.5 MB, post MLP+BN+ReLU features

// ---------------- packed f32x2 helpers (exact IEEE per lane) ----------------
__device__ __forceinline__ unsigned long long pack2(float lo, float hi) {
    unsigned long long r;
    asm("mov.b64 %0, {%1, %2};" : "=l"(r) : "f"(lo), "f"(hi));
    return r;
}
__device__ __forceinline__ void unpack2(unsigned long long v, float& lo, float& hi) {
    asm("mov.b64 {%0, %1}, %2;" : "=f"(lo), "=f"(hi) : "l"(v));
}
__device__ __forceinline__ unsigned long long add2(unsigned long long a, unsigned long long b) {
    unsigned long long r;
    asm("add.rn.f32x2 %0, %1, %2;" : "=l"(r) : "l"(a), "l"(b));
    return r;
}
__device__ __forceinline__ unsigned long long mul2(unsigned long long a, unsigned long long b) {
    unsigned long long r;
    asm("mul.rn.f32x2 %0, %1, %2;" : "=l"(r) : "l"(a), "l"(b));
    return r;
}
__device__ __forceinline__ unsigned smem_u32(const void* p) {
    return (unsigned)__cvta_generic_to_shared(p);
}

// ============================================================================
// 1) FPS — cluster of 2 CTAs per batch. Each CTA: 512 threads x 8 owned points
//    (registers, NEGATED: (-p)+c == -(p-c) exactly; squaring erases sign).
//    BOTH CTAs mirror the FULL 8192-point table in smem, so the cross-CTA
//    exchange is only an 8-byte key: (val_bits<<32) | ~global_idx — u64 max
//    == (max val, tie -> min idx), exactly jnp.argmax. Thread 0 pushes the key
//    with one st.shared::cluster.b64 + one st.release flag (monotonic i+1);
//    all threads poll the LOCAL flag with ld.acquire (broadcast LDS).
//    Winner coords: local LDS.128 from the full table. Bit-identical math.
// ============================================================================
extern __shared__ float4 s_pts[];   // [N_] full table, 128 KB dynamic

__global__ __launch_bounds__(FTPB_, 1) __cluster_dims__(FCTA_, 1, 1)
void fps_kernel(const float* __restrict__ coords, float* __restrict__ out_coords)
{
    __shared__ unsigned s_val[2][32];
    __shared__ unsigned s_idx[2][32];
    __shared__ unsigned long long x_key[2];   // peer-written candidate key
    __shared__ unsigned x_flag;               // monotonic iteration flag

    const int b    = blockIdx.x / FCTA_;
    const int rank = blockIdx.x % FCTA_;
    const int peer = 1 - rank;
    const int t    = threadIdx.x;
    const int lane = t & 31;
    const int w    = t >> 5;
    const float* cb = coords + (size_t)b * N_ * 3;
    const int base_pt = rank * FPPC_;

    // ---- load own 8 points into registers (negated, packed) + smem table ----
    unsigned long long npx[4], npy[4], npz[4];
    float pd[FPPT_];
    {
        float f[24];
        const float4* src = (const float4*)(cb + (size_t)base_pt * 3 + t * 24);
#pragma unroll
        for (int q = 0; q < 6; q++) {
            float4 v = src[q];
            f[q * 4 + 0] = v.x; f[q * 4 + 1] = v.y; f[q * 4 + 2] = v.z; f[q * 4 + 3] = v.w;
        }
#pragma unroll
        for (int j = 0; j < FPPT_; j++) {
            s_pts[base_pt + t * FPPT_ + j] = make_float4(f[3 * j], f[3 * j + 1], f[3 * j + 2], 0.0f);
            pd[j] = 1e10f;
        }
#pragma unroll
        for (int jj = 0; jj < 4; jj++) {
            npx[jj] = pack2(-f[6 * jj + 0], -f[6 * jj + 3]);
            npy[jj] = pack2(-f[6 * jj + 1], -f[6 * jj + 4]);
            npz[jj] = pack2(-f[6 * jj + 2], -f[6 * jj + 5]);
        }
    }
    // ---- mirror the other half into the table (smem only) ----
    {
        const int ob = peer * FPPC_;
        for (int p = t; p < FPPC_; p += FTPB_)
            s_pts[ob + p] = make_float4(cb[(ob + p) * 3 + 0], cb[(ob + p) * 3 + 1],
                                        cb[(ob + p) * 3 + 2], 0.0f);
    }
    // dummy level-2 slots for warps 16..31
    if (t >= 16 && t < 32) {
        s_val[0][t] = 0u;          s_val[1][t] = 0u;
        s_idx[0][t] = 0xffffffffu; s_idx[1][t] = 0xffffffffu;
    }
    if (t == 0) x_flag = 0u;
    __syncthreads();
    asm volatile("barrier.cluster.arrive.aligned;" ::: "memory");
    asm volatile("barrier.cluster.wait.aligned;"   ::: "memory");

    // peer exchange addresses (constant across iterations)
    unsigned pk0, pk1, pf;
    {
        unsigned lk0 = smem_u32(&x_key[0]);
        unsigned lk1 = smem_u32(&x_key[1]);
        unsigned lf  = smem_u32(&x_flag);
        asm("mapa.shared::cluster.u32 %0, %1, %2;" : "=r"(pk0) : "r"(lk0), "r"(peer));
        asm("mapa.shared::cluster.u32 %0, %1, %2;" : "=r"(pk1) : "r"(lk1), "r"(peer));
        asm("mapa.shared::cluster.u32 %0, %1, %2;" : "=r"(pf)  : "r"(lf),  "r"(peer));
    }
    const unsigned flag_l = smem_u32(&x_flag);

    const unsigned FULL = 0xffffffffu;
    unsigned g = 0u;
    float4   c = s_pts[0];

    for (int i = 0; i < S_; i++) {
        if (rank == 0 && t == 0) {
            g_fps_idx[b * S_ + i] = (int)g;
            float* oc = out_coords + ((size_t)b * S_ + i) * 3;
            oc[0] = c.x; oc[1] = c.y; oc[2] = c.z;
        }
        if (i == S_ - 1) break;

        const int buf = i & 1;

        // ---- distance update (exact IEEE: (-p)+c, mul, ((x+y)+z)) ----
        const unsigned long long cxx = pack2(c.x, c.x);
        const unsigned long long cyy = pack2(c.y, c.y);
        const unsigned long long czz = pack2(c.z, c.z);
#pragma unroll
        for (int jj = 0; jj < 4; jj++) {
            unsigned long long dx = add2(npx[jj], cxx);
            unsigned long long dy = add2(npy[jj], cyy);
            unsigned long long dz = add2(npz[jj], czz);
            unsigned long long dd = add2(add2(mul2(dx, dx), mul2(dy, dy)), mul2(dz, dz));
            float d0, d1;
            unpack2(dd, d0, d1);
            pd[2 * jj]     = fminf(pd[2 * jj],     d0);
            pd[2 * jj + 1] = fminf(pd[2 * jj + 1], d1);
        }

        // balanced local argmax over 8 (strict > keeps lower index on ties)
        float tv[FPPT_]; int ti[FPPT_];
#pragma unroll
        for (int j = 0; j < FPPT_; j++) { tv[j] = pd[j]; ti[j] = j; }
#pragma unroll
        for (int st = 1; st < FPPT_; st <<= 1)
#pragma unroll
            for (int j = 0; j < FPPT_; j += 2 * st)
                if (tv[j + st] > tv[j]) { tv[j] = tv[j + st]; ti[j] = ti[j + st]; }
        float m = tv[0];
        unsigned mi = (unsigned)(base_pt + t * FPPT_ + ti[0]);   // global index

        // warp argmax (d >= 0 -> float bits order-isomorphic to u32)
        unsigned mb = __float_as_uint(m);
        unsigned wm = __reduce_max_sync(FULL, mb);
        unsigned cand = (mb == wm) ? mi : 0xffffffffu;
        unsigned wmi = __reduce_min_sync(FULL, cand);
        if (lane == 0) { s_val[buf][w] = wm; s_idx[buf][w] = wmi; }
        __syncthreads();

        // CTA-level reduce (every warp, redundant, branch-free over 32 slots)
        unsigned v  = s_val[buf][lane];
        unsigned ix = s_idx[buf][lane];
        unsigned gm = __reduce_max_sync(FULL, v);
        unsigned c2 = (v == gm) ? ix : 0xffffffffu;
        unsigned gi = __reduce_min_sync(FULL, c2);
        unsigned long long kl =
            ((unsigned long long)gm << 32) | (unsigned long long)(~gi);

        // ---- exchange: thread 0 pushes local key to peer ----
        if (t == 0) {
            unsigned pk = buf ? pk1 : pk0;
            asm volatile("st.shared::cluster.b64 [%0], %1;" :: "r"(pk), "l"(kl) : "memory");
            asm volatile("st.release.cluster.shared::cluster.b32 [%0], %1;"
                         :: "r"(pf), "r"((unsigned)(i + 1)) : "memory");
        }

        // ---- all threads: wait for peer key (local flag, broadcast LDS) ----
        unsigned fv;
        do {
            asm volatile("ld.acquire.cluster.shared::cta.b32 %0, [%1];"
                         : "=r"(fv) : "r"(flag_l) : "memory");
        } while (fv < (unsigned)(i + 1));
        unsigned long long kr = x_key[buf];

        unsigned long long kw = (kr > kl) ? kr : kl;
        g = ~((unsigned)kw);
        c = s_pts[g];                 // full table -> local broadcast LDS.128
    }

    asm volatile("barrier.cluster.arrive.aligned;" ::: "memory");
    asm volatile("barrier.cluster.wait.aligned;"   ::: "memory");
}

// ============================================================================
// 2) KNN: K=16 smallest (d, idx) lexicographic (matches top_k(-d)).
// ============================================================================
__global__ __launch_bounds__(128)
void knn_kernel(const float* __restrict__ coords)
{
    const int b = blockIdx.y;
    const int s = blockIdx.x * 128 + threadIdx.x;
    const float* cb = coords + (size_t)b * N_ * 3;

    const int qi = g_fps_idx[b * S_ + s];
    const float qx = cb[qi * 3 + 0];
    const float qy = cb[qi * 3 + 1];
    const float qz = cb[qi * 3 + 2];

    __shared__ float4 tile[2048];     // 32 KB, padded xyz

    float dk[K_];
    int   ik[K_];
#pragma unroll
    for (int j = 0; j < K_; j++) { dk[j] = CUDART_INF_F; ik[j] = 0; }

    for (int t0 = 0; t0 < N_; t0 += 2048) {
        __syncthreads();
        for (int v = threadIdx.x; v < 2048; v += 128) {
            int p = t0 + v;
            tile[v] = make_float4(cb[p * 3 + 0], cb[p * 3 + 1], cb[p * 3 + 2], 0.0f);
        }
        __syncthreads();

#pragma unroll 8
        for (int p = 0; p < 2048; p++) {
            float4 cc = tile[p];
            float dx = __fsub_rn(qx, cc.x);
            float dy = __fsub_rn(qy, cc.y);
            float dz = __fsub_rn(qz, cc.z);
            float dd = __fadd_rn(__fadd_rn(__fmul_rn(dx, dx), __fmul_rn(dy, dy)),
                                 __fmul_rn(dz, dz));
            if (dd < dk[K_ - 1]) {
                float vd = dd; int vi = t0 + p;
#pragma unroll
                for (int j = 0; j < K_; j++) {
                    if (vd < dk[j]) {
                        float td = dk[j]; int ti2 = ik[j];
                        dk[j] = vd; ik[j] = vi;
                        vd = td; vi = ti2;
                    }
                }
            }
        }
    }

    int* out = &g_knn_idx[((size_t)b * S_ + s) * K_];
#pragma unroll
    for (int j = 0; j < K_; j++) out[j] = ik[j];
}

// ============================================================================
// 3) Pointwise MLP (64->128) + BN(eval) + ReLU on ALL points -> g_h.
// ============================================================================
__global__ __launch_bounds__(256)
void mlp_kernel(const float* __restrict__ features,
                const float* __restrict__ W,
                const float* __restrict__ bias,
                const float* __restrict__ gamma,
                const float* __restrict__ beta,
                const float* __restrict__ rmean,
                const float* __restrict__ rvar)
{
    const int pt0  = blockIdx.x * 32;
    const int o    = threadIdx.x & 127;
    const int half = threadIdx.x >> 7;

    __shared__ float sW[DOUT_ * DIN_];          // 32 KB
    __shared__ float sF[32 * DIN_];             // 8 KB

    for (int v = threadIdx.x; v < DOUT_ * DIN_; v += 256) sW[v] = W[v];
    for (int v = threadIdx.x; v < 32 * DIN_;   v += 256) sF[v] = features[(size_t)pt0 * DIN_ + v];
    __syncthreads();

    float w[DIN_];
#pragma unroll
    for (int d = 0; d < DIN_; d++) w[d] = sW[o * DIN_ + d];

    const float bo = bias[o];
    const float mn = rmean[o];
    const float sc = gamma[o] * rsqrtf(rvar[o] + BN_EPS_);
    const float bt = beta[o];

    for (int p = half * 16; p < half * 16 + 16; p++) {
        float acc = 0.0f;
#pragma unroll
        for (int d = 0; d < DIN_; d += 4) {
            float4 f = *(const float4*)&sF[p * DIN_ + d];
            acc = fmaf(w[d + 0], f.x, acc);
            acc = fmaf(w[d + 1], f.y, acc);
            acc = fmaf(w[d + 2], f.z, acc);
            acc = fmaf(w[d + 3], f.w, acc);
        }
        float lin = acc + bo;
        float val = (lin - mn) * sc + bt;
        g_h[((size_t)pt0 + p) * DOUT_ + o] = fmaxf(val, 0.0f);
    }
}

// ============================================================================
// 4) Gather K neighbors' features + max-pool.
// ============================================================================
__global__ __launch_bounds__(256)
void pool_kernel(float* __restrict__ out_feat)
{
    const int b   = blockIdx.y;
    const int s   = blockIdx.x * 8 + (threadIdx.x >> 5);
    const int col = threadIdx.x & 31;

    const int* kid = &g_knn_idx[((size_t)b * S_ + s) * K_];

    float4 acc = make_float4(-CUDART_INF_F, -CUDART_INF_F, -CUDART_INF_F, -CUDART_INF_F);
#pragma unroll
    for (int k = 0; k < K_; k++) {
        const int id = kid[k];
        const float4 v = *(const float4*)&g_h[((size_t)b * N_ + id) * DOUT_ + col * 4];
        acc.x = fmaxf(acc.x, v.x);
        acc.y = fmaxf(acc.y, v.y);
        acc.z = fmaxf(acc.z, v.z);
        acc.w = fmaxf(acc.w, v.w);
    }
    *(float4*)&out_feat[((size_t)b * S_ + s) * DOUT_ + col * 4] = acc;
}

// ============================================================================
extern "C" void kernel_launch(void* const* d_in, const int* in_sizes, int n_in,
                              void* d_out, int out_size)
{
    const float* coords   = (const float*)d_in[0];
    const float* features = (const float*)d_in[1];
    const float* W        = (const float*)d_in[2];
    const float* bias     = (const float*)d_in[3];
    const float* gamma    = (const float*)d_in[4];
    const float* beta     = (const float*)d_in[5];
    const float* rmean    = (const float*)d_in[6];
    const float* rvar     = (const float*)d_in[7];

    float* out        = (float*)d_out;
    float* out_coords = out;                       // [B, S, 3]
    float* out_feat   = out + (size_t)B_ * S_ * 3; // [B, S, 128]

    static bool attr_done = false;
    if (!attr_done) {
        cudaFuncSetAttribute(fps_kernel, cudaFuncAttributeMaxDynamicSharedMemorySize,
                             N_ * (int)sizeof(float4));
        attr_done = true;
    }

    fps_kernel<<<B_ * FCTA_, FTPB_, N_ * sizeof(float4)>>>(coords, out_coords);
    mlp_kernel<<<(B_ * N_) / 32, 256>>>(features, W, bias, gamma, beta, rmean, rvar);
    knn_kernel<<<dim3(S_ / 128, B_), 128>>>(coords);
    pool_kernel<<<dim3(S_ / 8, B_), 256>>>(out_feat);
}